// round 13
// baseline (speedup 1.0000x reference)
#include <cuda_runtime.h>
#include <cuda_fp16.h>
#include <math.h>
#include <stdint.h>

#define N_NODES 50000
#define N_EDGES 800000
#define F_INDIM 128
#define HID 256
#define BN_EPS 1e-5f
#define SCAN_NB 49   // ceil(50000/1024)

// ---------------- scratch (device globals: no allocation allowed) ----------------
__device__ int    g_rowptr[N_NODES + 1];
__device__ int    g_cursor[N_NODES];
__device__ int    g_bsum[64];
__device__ int    g_col[N_EDGES];
__device__ float  g_h[(size_t)N_NODES * HID];          // pre-BN activations (fp32)
__device__ __half g_A[(size_t)N_NODES * 512];          // fp16 A: cols[0:256)=agg, [256:512)=root/gather
__device__ __half g_B[3 * (size_t)HID * 512];          // fp16 B per layer = [Wn;Wr]^T, row stride 512
__device__ float  g_stats[3 * 512];                    // per layer: [0:256)=sum, [256:512)=sumsq

// ---------------- small helpers ----------------
__device__ __forceinline__ uint32_t smem_u32(const void* p) {
    uint32_t a;
    asm("{ .reg .u64 t; cvta.to.shared.u64 t, %1; cvt.u32.u64 %0, t; }" : "=r"(a) : "l"(p));
    return a;
}
__device__ __forceinline__ void cp16(uint32_t dst, const void* src) {
    asm volatile("cp.async.cg.shared.global [%0], [%1], 16;" :: "r"(dst), "l"(src) : "memory");
}
__device__ __forceinline__ void cpa_commit() {
    asm volatile("cp.async.commit_group;" ::: "memory");
}
template <int NN>
__device__ __forceinline__ void cpa_wait() {
    asm volatile("cp.async.wait_group %0;" :: "n"(NN) : "memory");
}
__device__ __forceinline__ void ldm_x4(uint32_t* r, uint32_t addr) {
    asm volatile("ldmatrix.sync.aligned.m8n8.x4.shared.b16 {%0,%1,%2,%3}, [%4];"
                 : "=r"(r[0]), "=r"(r[1]), "=r"(r[2]), "=r"(r[3]) : "r"(addr));
}
__device__ __forceinline__ void mma_fp16(float* d, const uint32_t* a, const uint32_t* b) {
    asm volatile("mma.sync.aligned.m16n8k16.row.col.f32.f16.f16.f32 "
                 "{%0,%1,%2,%3}, {%4,%5,%6,%7}, {%8,%9}, {%0,%1,%2,%3};"
                 : "+f"(d[0]), "+f"(d[1]), "+f"(d[2]), "+f"(d[3])
                 : "r"(a[0]), "r"(a[1]), "r"(a[2]), "r"(a[3]), "r"(b[0]), "r"(b[1]));
}

// ---------------- prep: zero edge counters + all 3 stats buffers ----------------
__global__ void prep_kernel() {
    int i = blockIdx.x * blockDim.x + threadIdx.x;
    if (i < N_NODES) g_cursor[i] = 0;
    if (i < 3 * 512) g_stats[i] = 0.0f;
}
__global__ void count_kernel(const int* __restrict__ ei) {
    int e = blockIdx.x * blockDim.x + threadIdx.x;
    if (e < N_EDGES) atomicAdd(&g_cursor[ei[N_EDGES + e]], 1);
}
// ---- multi-block scan: phase 1 ----
__global__ void scan1_kernel() {
    __shared__ int sh[1024];
    int tid = threadIdx.x;
    int i = blockIdx.x * 1024 + tid;
    int v = (i < N_NODES) ? g_cursor[i] : 0;
    sh[tid] = v;
    __syncthreads();
    for (int off = 1; off < 1024; off <<= 1) {
        int t = (tid >= off) ? sh[tid - off] : 0;
        __syncthreads();
        sh[tid] += t;
        __syncthreads();
    }
    if (i < N_NODES) g_rowptr[i] = sh[tid] - v;
    if (tid == 1023) g_bsum[blockIdx.x] = sh[1023];
}
// ---- phase 2 ----
__global__ void scan2_kernel() {
    __shared__ int sh[64];
    int tid = threadIdx.x;
    int v = (tid < SCAN_NB) ? g_bsum[tid] : 0;
    sh[tid] = v;
    __syncthreads();
    for (int off = 1; off < 64; off <<= 1) {
        int t = (tid >= off) ? sh[tid - off] : 0;
        __syncthreads();
        sh[tid] += t;
        __syncthreads();
    }
    if (tid < SCAN_NB) g_bsum[tid] = sh[tid] - v;
    if (tid == 63) g_rowptr[N_NODES] = sh[63];
}
// ---- phase 3 ----
__global__ void scan3_kernel() {
    int i = blockIdx.x * 1024 + threadIdx.x;
    if (i < N_NODES) {
        int r = g_rowptr[i] + g_bsum[blockIdx.x];
        g_rowptr[i] = r;
        g_cursor[i] = r;
    }
}
__global__ void scatter_kernel(const int* __restrict__ ei) {
    int e = blockIdx.x * blockDim.x + threadIdx.x;
    if (e < N_EDGES) {
        int s = ei[e];
        int d = ei[N_EDGES + e];
        g_col[atomicAdd(&g_cursor[d], 1)] = s;
    }
}

// ---------------- convert x -> fp16 root cols A[:,128:256) ----------------
__global__ void convert_x_kernel(const float* __restrict__ x) {
    int i = blockIdx.x * blockDim.x + threadIdx.x;     // over N*32
    if (i >= N_NODES * 32) return;
    int row = i >> 5, grp = i & 31;
    const float4 v = __ldg((const float4*)(x + (size_t)row * 128 + grp * 4));
    __half2 h01 = __floats2half2_rn(v.x, v.y);
    __half2 h23 = __floats2half2_rn(v.z, v.w);
    uint2 u;
    u.x = *reinterpret_cast<uint32_t*>(&h01);
    u.y = *reinterpret_cast<uint32_t*>(&h23);
    *(uint2*)(g_A + (size_t)row * 512 + 128 + grp * 4) = u;
}

// ---------------- convert all 3 layers' weights upfront ----------------
__global__ void convert_w_all_kernel(const float* __restrict__ Wn0, const float* __restrict__ Wr0,
                                     const float* __restrict__ Wn1, const float* __restrict__ Wr1,
                                     const float* __restrict__ Wn2, const float* __restrict__ Wr2) {
    int i = blockIdx.x * blockDim.x + threadIdx.x;   // over 3 * 256 * 512
    if (i >= 3 * HID * 512) return;
    int l = i >> 17;           // / (256*512)
    int j = i & 131071;
    int n = j >> 9;            // / 512
    int k = j & 511;
    int DIN  = (l == 0) ? 128 : 256;
    int KEXT = (l == 0) ? 256 : 512;
    if (k >= KEXT) return;
    const float* Wn = (l == 0) ? Wn0 : (l == 1) ? Wn1 : Wn2;
    const float* Wr = (l == 0) ? Wr0 : (l == 1) ? Wr1 : Wr2;
    float w = (k < DIN) ? Wn[(size_t)k * HID + n] : Wr[(size_t)(k - DIN) * HID + n];
    g_B[(size_t)l * 131072 + (size_t)n * 512 + k] = __float2half_rn(w);
}

// ---------------- layer0 aggregation: gather x (cols 128-255), write agg cols 0-127 ----------------
__global__ void agg0_kernel() {
    int gw   = (blockIdx.x * blockDim.x + threadIdx.x) >> 5;
    int lane = threadIdx.x & 31;
    if (gw >= N_NODES) return;
    int beg = g_rowptr[gw];
    int end = g_rowptr[gw + 1];

    float a[4] = {0.f, 0.f, 0.f, 0.f};
    float b[4] = {0.f, 0.f, 0.f, 0.f};
    int e = beg;
    for (; e + 1 < end; e += 2) {
        int s0 = g_col[e], s1 = g_col[e + 1];
        uint2 u0 = __ldg((const uint2*)(g_A + (size_t)s0 * 512 + 128) + lane);
        uint2 u1 = __ldg((const uint2*)(g_A + (size_t)s1 * 512 + 128) + lane);
        __half2 p0 = *reinterpret_cast<__half2*>(&u0.x);
        __half2 p1 = *reinterpret_cast<__half2*>(&u0.y);
        __half2 q0 = *reinterpret_cast<__half2*>(&u1.x);
        __half2 q1 = *reinterpret_cast<__half2*>(&u1.y);
        float2 f0 = __half22float2(p0), f1 = __half22float2(p1);
        float2 g0 = __half22float2(q0), g1 = __half22float2(q1);
        a[0] += f0.x; a[1] += f0.y; a[2] += f1.x; a[3] += f1.y;
        b[0] += g0.x; b[1] += g0.y; b[2] += g1.x; b[3] += g1.y;
    }
    if (e < end) {
        int s0 = g_col[e];
        uint2 u0 = __ldg((const uint2*)(g_A + (size_t)s0 * 512 + 128) + lane);
        __half2 p0 = *reinterpret_cast<__half2*>(&u0.x);
        __half2 p1 = *reinterpret_cast<__half2*>(&u0.y);
        float2 f0 = __half22float2(p0), f1 = __half22float2(p1);
        a[0] += f0.x; a[1] += f0.y; a[2] += f1.x; a[3] += f1.y;
    }
    float inv = 1.0f / fmaxf((float)(end - beg), 1.0f);
    __half2 o01 = __floats2half2_rn((a[0] + b[0]) * inv, (a[1] + b[1]) * inv);
    __half2 o23 = __floats2half2_rn((a[2] + b[2]) * inv, (a[3] + b[3]) * inv);
    uint2 u;
    u.x = *reinterpret_cast<uint32_t*>(&o01);
    u.y = *reinterpret_cast<uint32_t*>(&o23);
    *(uint2*)(g_A + (size_t)gw * 512 + lane * 4) = u;
}

// ---------------- layers 1/2 aggregation: gather root cols 256-511, write agg cols 0-255 ----------------
__global__ void agg_bf_kernel() {
    int gw   = (blockIdx.x * blockDim.x + threadIdx.x) >> 5;
    int lane = threadIdx.x & 31;
    if (gw >= N_NODES) return;
    int beg = g_rowptr[gw];
    int end = g_rowptr[gw + 1];

    float a[8] = {0.f, 0.f, 0.f, 0.f, 0.f, 0.f, 0.f, 0.f};
    float b[8] = {0.f, 0.f, 0.f, 0.f, 0.f, 0.f, 0.f, 0.f};
    int e = beg;
    for (; e + 1 < end; e += 2) {
        int s0 = g_col[e], s1 = g_col[e + 1];
        uint4 u = __ldg((const uint4*)(g_A + (size_t)s0 * 512 + 256) + lane);
        uint4 v = __ldg((const uint4*)(g_A + (size_t)s1 * 512 + 256) + lane);
        __half2 h0 = *reinterpret_cast<__half2*>(&u.x);
        __half2 h1 = *reinterpret_cast<__half2*>(&u.y);
        __half2 h2 = *reinterpret_cast<__half2*>(&u.z);
        __half2 h3 = *reinterpret_cast<__half2*>(&u.w);
        float2 f0 = __half22float2(h0), f1 = __half22float2(h1);
        float2 f2 = __half22float2(h2), f3 = __half22float2(h3);
        a[0] += f0.x; a[1] += f0.y; a[2] += f1.x; a[3] += f1.y;
        a[4] += f2.x; a[5] += f2.y; a[6] += f3.x; a[7] += f3.y;
        __half2 k0 = *reinterpret_cast<__half2*>(&v.x);
        __half2 k1 = *reinterpret_cast<__half2*>(&v.y);
        __half2 k2 = *reinterpret_cast<__half2*>(&v.z);
        __half2 k3 = *reinterpret_cast<__half2*>(&v.w);
        float2 g0 = __half22float2(k0), g1 = __half22float2(k1);
        float2 g2 = __half22float2(k2), g3 = __half22float2(k3);
        b[0] += g0.x; b[1] += g0.y; b[2] += g1.x; b[3] += g1.y;
        b[4] += g2.x; b[5] += g2.y; b[6] += g3.x; b[7] += g3.y;
    }
    if (e < end) {
        int s0 = g_col[e];
        uint4 u = __ldg((const uint4*)(g_A + (size_t)s0 * 512 + 256) + lane);
        __half2 h0 = *reinterpret_cast<__half2*>(&u.x);
        __half2 h1 = *reinterpret_cast<__half2*>(&u.y);
        __half2 h2 = *reinterpret_cast<__half2*>(&u.z);
        __half2 h3 = *reinterpret_cast<__half2*>(&u.w);
        float2 f0 = __half22float2(h0), f1 = __half22float2(h1);
        float2 f2 = __half22float2(h2), f3 = __half22float2(h3);
        a[0] += f0.x; a[1] += f0.y; a[2] += f1.x; a[3] += f1.y;
        a[4] += f2.x; a[5] += f2.y; a[6] += f3.x; a[7] += f3.y;
    }
    float inv = 1.0f / fmaxf((float)(end - beg), 1.0f);
    __half2 o0 = __floats2half2_rn((a[0] + b[0]) * inv, (a[1] + b[1]) * inv);
    __half2 o1 = __floats2half2_rn((a[2] + b[2]) * inv, (a[3] + b[3]) * inv);
    __half2 o2 = __floats2half2_rn((a[4] + b[4]) * inv, (a[5] + b[5]) * inv);
    __half2 o3 = __floats2half2_rn((a[6] + b[6]) * inv, (a[7] + b[7]) * inv);
    uint4 u;
    u.x = *reinterpret_cast<uint32_t*>(&o0);
    u.y = *reinterpret_cast<uint32_t*>(&o1);
    u.z = *reinterpret_cast<uint32_t*>(&o2);
    u.w = *reinterpret_cast<uint32_t*>(&o3);
    *(uint4*)(g_A + (size_t)gw * 512 + lane * 8) = u;
}

// ---------------- fp16 HMMA GEMM, CTA tile 128x256, fused BN-stats epilogue ----------------
// 512 threads = 16 warps (4m x 4n), warp tile 32x64, K-chunk 32, double-buffered cp.async.
#define SA 40                        // smem halves per row (32 + 8 pad)
#define OF_B  10240u                 // A region: 128*40*2
#define BUFB  30720u                 // + B region: 256*40*2
#define SM_GEMM (2 * 30720)

template <int KT>   // k-extent: 256 (layer0) or 512; row stride is always 512
__global__ void __launch_bounds__(512, 2)
hmma_gemm_kernel(const __half* __restrict__ A, const __half* __restrict__ B,
                 const float* __restrict__ bias, float* __restrict__ C,
                 float* __restrict__ stats) {
    extern __shared__ char smem[];
    const uint32_t sb = smem_u32(smem);
    const int tid  = threadIdx.x;
    const int lane = tid & 31;
    const int wid  = tid >> 5;
    const int wm   = wid & 3;     // 0..3 -> m offset wm*32
    const int wn   = wid >> 2;    // 0..3 -> n offset wn*64
    const int bm   = blockIdx.x * 128;

    float acc[2][8][4];
#pragma unroll
    for (int a = 0; a < 2; a++)
#pragma unroll
        for (int b = 0; b < 8; b++)
#pragma unroll
            for (int c = 0; c < 4; c++) acc[a][b][c] = 0.0f;

    auto issue = [&](int buf, int k0) {
        uint32_t base = sb + buf * BUFB;
        // A: 128 rows x 4 sectors = 512 cp16 (v=0)
        {
            int r = tid >> 2, s = tid & 3;
            int grow = bm + r;
            if (grow >= N_NODES) grow = N_NODES - 1;   // clamp; excluded in epilogue
            cp16(base + (uint32_t)(r * SA + s * 8) * 2, A + (size_t)grow * 512 + k0 + s * 8);
        }
        // B: 256 rows x 4 sectors = 1024 cp16 (v=1,2)
#pragma unroll
        for (int v = 0; v < 2; v++) {
            int idx = v * 512 + tid;
            int r = idx >> 2, s = idx & 3;
            cp16(base + OF_B + (uint32_t)(r * SA + s * 8) * 2, B + (size_t)r * 512 + k0 + s * 8);
        }
    };

    const int nch = KT / 32;
    issue(0, 0);
    cpa_commit();
    int buf = 0;
    for (int ch = 0; ch < nch; ch++) {
        if (ch + 1 < nch) {
            issue(buf ^ 1, (ch + 1) * 32);
            cpa_commit();
            cpa_wait<1>();
        } else {
            cpa_wait<0>();
        }
        __syncthreads();
        uint32_t base = sb + buf * BUFB;
#pragma unroll
        for (int ks = 0; ks < 2; ks++) {
            const int kc = ks * 16;
            uint32_t ah[2][4];
#pragma unroll
            for (int mt = 0; mt < 2; mt++) {
                int row = wm * 32 + mt * 16 + (lane & 15);
                int col = kc + ((lane >> 4) << 3);
                ldm_x4(ah[mt], base + (uint32_t)(row * SA + col) * 2);
            }
#pragma unroll
            for (int g = 0; g < 4; g++) {
                int nrow = wn * 64 + g * 16 + ((lane >> 4) << 3) + (lane & 7);
                int kcol = kc + (((lane >> 3) & 1) << 3);
                uint32_t bh4[4];
                ldm_x4(bh4, base + OF_B + (uint32_t)(nrow * SA + kcol) * 2);
#pragma unroll
                for (int mt = 0; mt < 2; mt++)
#pragma unroll
                    for (int s = 0; s < 2; s++)
                        mma_fp16(acc[mt][g * 2 + s], ah[mt], &bh4[s * 2]);
            }
        }
        __syncthreads();
        buf ^= 1;
    }

    // ---- epilogue: write C (+bias) and fused BN column stats (float) ----
    float* ssum = (float*)smem;          // [256]
    float* ssq  = ssum + 256;            // [256]
    if (tid < 256) { ssum[tid] = 0.0f; ssq[tid] = 0.0f; }
    __syncthreads();

#pragma unroll
    for (int nt = 0; nt < 8; nt++) {
        int col = wn * 64 + nt * 8 + (lane & 3) * 2;
        float b0 = __ldg(&bias[col]);
        float b1 = __ldg(&bias[col + 1]);
        float p0 = 0.f, p1 = 0.f, q0 = 0.f, q1 = 0.f;
#pragma unroll
        for (int mt = 0; mt < 2; mt++) {
            int row0 = bm + wm * 32 + mt * 16 + (lane >> 2);
            float c0 = acc[mt][nt][0] + b0;
            float c1 = acc[mt][nt][1] + b1;
            float c2 = acc[mt][nt][2] + b0;
            float c3 = acc[mt][nt][3] + b1;
            if (row0 < N_NODES) {
                C[(size_t)row0 * HID + col]     = c0;
                C[(size_t)row0 * HID + col + 1] = c1;
                p0 += c0; q0 += c0 * c0;
                p1 += c1; q1 += c1 * c1;
            }
            if (row0 + 8 < N_NODES) {
                C[(size_t)(row0 + 8) * HID + col]     = c2;
                C[(size_t)(row0 + 8) * HID + col + 1] = c3;
                p0 += c2; q0 += c2 * c2;
                p1 += c3; q1 += c3 * c3;
            }
        }
#pragma unroll
        for (int m = 4; m < 32; m <<= 1) {
            p0 += __shfl_xor_sync(0xFFFFFFFFu, p0, m);
            p1 += __shfl_xor_sync(0xFFFFFFFFu, p1, m);
            q0 += __shfl_xor_sync(0xFFFFFFFFu, q0, m);
            q1 += __shfl_xor_sync(0xFFFFFFFFu, q1, m);
        }
        if (lane < 4) {
            int lc = wn * 64 + nt * 8 + lane * 2;
            atomicAdd(&ssum[lc], p0);     atomicAdd(&ssq[lc], q0);
            atomicAdd(&ssum[lc + 1], p1); atomicAdd(&ssq[lc + 1], q1);
        }
    }
    __syncthreads();
    if (tid < 256) {
        atomicAdd(&stats[tid],       ssum[tid]);
        atomicAdd(&stats[256 + tid], ssq[tid]);
    }
}

// ---------------- normalize + ELU ----------------
// write_mode: 0 = fp16 root cols of g_A (layers 0/1), 1 = fp32 out (final layer)
__global__ void norm_elu_kernel(const float* __restrict__ h,
                                const float* __restrict__ gamma,
                                const float* __restrict__ beta,
                                const float* __restrict__ stats,
                                float* __restrict__ out,
                                int write_mode) {
    __shared__ float sscale[HID];
    __shared__ float sshift[HID];
    int tid = threadIdx.x;   // 256
    {
        double mu  = (double)stats[tid] * (1.0 / N_NODES);
        double var = (double)stats[256 + tid] * (1.0 / N_NODES) - mu * mu;
        float sc = gamma[tid] * rsqrtf((float)var + BN_EPS);
        sscale[tid] = sc;
        sshift[tid] = beta[tid] - (float)mu * sc;
    }
    __syncthreads();
    int r0 = blockIdx.x * 64;
    int r1 = min(r0 + 64, N_NODES);
    float sc = sscale[tid];
    float sh = sshift[tid];
    for (int r = r0; r < r1; r++) {
        size_t idx = (size_t)r * HID + tid;
        float v = h[idx] * sc + sh;
        float o = (v > 0.0f) ? v : expm1f(v);
        if (write_mode == 1) {
            out[idx] = o;
        } else {
            g_A[(size_t)r * 512 + 256 + tid] = __float2half_rn(o);
        }
    }
}

// ---------------- launch ----------------
extern "C" void kernel_launch(void* const* d_in, const int* in_sizes, int n_in,
                              void* d_out, int out_size) {
    (void)in_sizes; (void)n_in; (void)out_size;
    const float* x  = (const float*)d_in[0];
    const int*   ei = (const int*)d_in[1];
    const float* Wn[3] = {(const float*)d_in[2], (const float*)d_in[7],  (const float*)d_in[12]};
    const float* bn[3] = {(const float*)d_in[3], (const float*)d_in[8],  (const float*)d_in[13]};
    const float* Wr[3] = {(const float*)d_in[4], (const float*)d_in[9],  (const float*)d_in[14]};
    const float* gg[3] = {(const float*)d_in[5], (const float*)d_in[10], (const float*)d_in[15]};
    const float* bb[3] = {(const float*)d_in[6], (const float*)d_in[11], (const float*)d_in[16]};
    float* out = (float*)d_out;

    float *h_p, *stats_p;
    __half *A_p, *B_p;
    cudaGetSymbolAddress((void**)&h_p,     g_h);
    cudaGetSymbolAddress((void**)&stats_p, g_stats);
    cudaGetSymbolAddress((void**)&A_p,     g_A);
    cudaGetSymbolAddress((void**)&B_p,     g_B);

    cudaFuncSetAttribute(hmma_gemm_kernel<256>, cudaFuncAttributeMaxDynamicSharedMemorySize, SM_GEMM);
    cudaFuncSetAttribute(hmma_gemm_kernel<512>, cudaFuncAttributeMaxDynamicSharedMemorySize, SM_GEMM);

    const int TB = 256;
    const int nb_nodes = (N_NODES + TB - 1) / TB;
    const int nb_edges = (N_EDGES + TB - 1) / TB;
    const int agg_blocks = (N_NODES * 32 + TB - 1) / TB;
    const int cx_blocks  = (N_NODES * 32 + TB - 1) / TB;
    const int cw_blocks  = (3 * HID * 512 + TB - 1) / TB;
    const int norm_blocks = (N_NODES + 63) / 64;
    const int gemm_blocks = (N_NODES + 127) / 128;

    // ---- CSR build + zeroing + upfront converts ----
    prep_kernel<<<nb_nodes, TB>>>();
    count_kernel<<<nb_edges, TB>>>(ei);
    scan1_kernel<<<SCAN_NB, 1024>>>();
    scan2_kernel<<<1, 64>>>();
    scan3_kernel<<<SCAN_NB, 1024>>>();
    scatter_kernel<<<nb_edges, TB>>>(ei);
    convert_x_kernel<<<cx_blocks, TB>>>(x);
    convert_w_all_kernel<<<cw_blocks, TB>>>(Wn[0], Wr[0], Wn[1], Wr[1], Wn[2], Wr[2]);

    // ---- layer 0 (KEXT=256) ----
    agg0_kernel<<<agg_blocks, TB>>>();
    hmma_gemm_kernel<256><<<gemm_blocks, 512, SM_GEMM>>>(A_p, B_p, bn[0], h_p, stats_p);
    norm_elu_kernel<<<norm_blocks, HID>>>(h_p, gg[0], bb[0], stats_p, nullptr, 0);

    // ---- layer 1 (KEXT=512) ----
    agg_bf_kernel<<<agg_blocks, TB>>>();
    hmma_gemm_kernel<512><<<gemm_blocks, 512, SM_GEMM>>>(A_p, B_p + 131072, bn[1], h_p, stats_p + 512);
    norm_elu_kernel<<<norm_blocks, HID>>>(h_p, gg[1], bb[1], stats_p + 512, nullptr, 0);

    // ---- layer 2 (KEXT=512) ----
    agg_bf_kernel<<<agg_blocks, TB>>>();
    hmma_gemm_kernel<512><<<gemm_blocks, 512, SM_GEMM>>>(A_p, B_p + 2 * 131072, bn[2], out, stats_p + 1024);
    norm_elu_kernel<<<norm_blocks, HID>>>(out, gg[2], bb[2], stats_p + 1024, out, 1);
}

// round 15
// speedup vs baseline: 1.5881x; 1.5881x over previous
#include <cuda_runtime.h>
#include <cuda_fp16.h>
#include <math.h>
#include <stdint.h>

#define N_NODES 50000
#define N_EDGES 800000
#define F_INDIM 128
#define HID 256
#define BN_EPS 1e-5f
#define SCAN_NB 49   // ceil(50000/1024)

// ---------------- scratch (device globals: no allocation allowed) ----------------
__device__ int    g_rowptr[N_NODES + 1];
__device__ int    g_cursor[N_NODES];
__device__ int    g_bsum[64];
__device__ int    g_col[N_EDGES];
__device__ float  g_h[(size_t)N_NODES * HID];          // pre-BN activations (fp32)
__device__ __half g_A[(size_t)N_NODES * 512];          // fp16 A: cols[0:256)=agg, [256:512)=root/gather
__device__ __half g_B[3 * (size_t)HID * 512];          // fp16 B per layer = [Wn;Wr]^T, row stride 512
__device__ float  g_stats[3 * 512];                    // per layer: [0:256)=sum, [256:512)=sumsq

// ---------------- small helpers ----------------
__device__ __forceinline__ uint32_t smem_u32(const void* p) {
    uint32_t a;
    asm("{ .reg .u64 t; cvta.to.shared.u64 t, %1; cvt.u32.u64 %0, t; }" : "=r"(a) : "l"(p));
    return a;
}
__device__ __forceinline__ void cp16(uint32_t dst, const void* src) {
    asm volatile("cp.async.cg.shared.global [%0], [%1], 16;" :: "r"(dst), "l"(src) : "memory");
}
__device__ __forceinline__ void cpa_commit() {
    asm volatile("cp.async.commit_group;" ::: "memory");
}
template <int NN>
__device__ __forceinline__ void cpa_wait() {
    asm volatile("cp.async.wait_group %0;" :: "n"(NN) : "memory");
}
__device__ __forceinline__ void ldm_x4(uint32_t* r, uint32_t addr) {
    asm volatile("ldmatrix.sync.aligned.m8n8.x4.shared.b16 {%0,%1,%2,%3}, [%4];"
                 : "=r"(r[0]), "=r"(r[1]), "=r"(r[2]), "=r"(r[3]) : "r"(addr));
}
__device__ __forceinline__ void mma_fp16(float* d, const uint32_t* a, const uint32_t* b) {
    asm volatile("mma.sync.aligned.m16n8k16.row.col.f32.f16.f16.f32 "
                 "{%0,%1,%2,%3}, {%4,%5,%6,%7}, {%8,%9}, {%0,%1,%2,%3};"
                 : "+f"(d[0]), "+f"(d[1]), "+f"(d[2]), "+f"(d[3])
                 : "r"(a[0]), "r"(a[1]), "r"(a[2]), "r"(a[3]), "r"(b[0]), "r"(b[1]));
}

// ---------------- prep: zero edge counters + all 3 stats buffers ----------------
__global__ void prep_kernel() {
    int i = blockIdx.x * blockDim.x + threadIdx.x;
    if (i < N_NODES) g_cursor[i] = 0;
    if (i < 3 * 512) g_stats[i] = 0.0f;
}
__global__ void count_kernel(const int* __restrict__ ei) {
    int e = blockIdx.x * blockDim.x + threadIdx.x;
    if (e < N_EDGES) atomicAdd(&g_cursor[ei[N_EDGES + e]], 1);
}
// ---- multi-block scan: phase 1 ----
__global__ void scan1_kernel() {
    __shared__ int sh[1024];
    int tid = threadIdx.x;
    int i = blockIdx.x * 1024 + tid;
    int v = (i < N_NODES) ? g_cursor[i] : 0;
    sh[tid] = v;
    __syncthreads();
    for (int off = 1; off < 1024; off <<= 1) {
        int t = (tid >= off) ? sh[tid - off] : 0;
        __syncthreads();
        sh[tid] += t;
        __syncthreads();
    }
    if (i < N_NODES) g_rowptr[i] = sh[tid] - v;
    if (tid == 1023) g_bsum[blockIdx.x] = sh[1023];
}
// ---- phase 2 ----
__global__ void scan2_kernel() {
    __shared__ int sh[64];
    int tid = threadIdx.x;
    int v = (tid < SCAN_NB) ? g_bsum[tid] : 0;
    sh[tid] = v;
    __syncthreads();
    for (int off = 1; off < 64; off <<= 1) {
        int t = (tid >= off) ? sh[tid - off] : 0;
        __syncthreads();
        sh[tid] += t;
        __syncthreads();
    }
    if (tid < SCAN_NB) g_bsum[tid] = sh[tid] - v;
    if (tid == 63) g_rowptr[N_NODES] = sh[63];
}
// ---- phase 3 ----
__global__ void scan3_kernel() {
    int i = blockIdx.x * 1024 + threadIdx.x;
    if (i < N_NODES) {
        int r = g_rowptr[i] + g_bsum[blockIdx.x];
        g_rowptr[i] = r;
        g_cursor[i] = r;
    }
}
__global__ void scatter_kernel(const int* __restrict__ ei) {
    int e = blockIdx.x * blockDim.x + threadIdx.x;
    if (e < N_EDGES) {
        int s = ei[e];
        int d = ei[N_EDGES + e];
        g_col[atomicAdd(&g_cursor[d], 1)] = s;
    }
}

// ---------------- convert x -> fp16 root cols A[:,128:256) ----------------
__global__ void convert_x_kernel(const float* __restrict__ x) {
    int i = blockIdx.x * blockDim.x + threadIdx.x;     // over N*32
    if (i >= N_NODES * 32) return;
    int row = i >> 5, grp = i & 31;
    const float4 v = __ldg((const float4*)(x + (size_t)row * 128 + grp * 4));
    __half2 h01 = __floats2half2_rn(v.x, v.y);
    __half2 h23 = __floats2half2_rn(v.z, v.w);
    uint2 u;
    u.x = *reinterpret_cast<uint32_t*>(&h01);
    u.y = *reinterpret_cast<uint32_t*>(&h23);
    *(uint2*)(g_A + (size_t)row * 512 + 128 + grp * 4) = u;
}

// ---------------- convert all 3 layers' weights upfront ----------------
__global__ void convert_w_all_kernel(const float* __restrict__ Wn0, const float* __restrict__ Wr0,
                                     const float* __restrict__ Wn1, const float* __restrict__ Wr1,
                                     const float* __restrict__ Wn2, const float* __restrict__ Wr2) {
    int i = blockIdx.x * blockDim.x + threadIdx.x;   // over 3 * 256 * 512
    if (i >= 3 * HID * 512) return;
    int l = i >> 17;           // / (256*512)
    int j = i & 131071;
    int n = j >> 9;            // / 512
    int k = j & 511;
    int DIN  = (l == 0) ? 128 : 256;
    int KEXT = (l == 0) ? 256 : 512;
    if (k >= KEXT) return;
    const float* Wn = (l == 0) ? Wn0 : (l == 1) ? Wn1 : Wn2;
    const float* Wr = (l == 0) ? Wr0 : (l == 1) ? Wr1 : Wr2;
    float w = (k < DIN) ? Wn[(size_t)k * HID + n] : Wr[(size_t)(k - DIN) * HID + n];
    g_B[(size_t)l * 131072 + (size_t)n * 512 + k] = __float2half_rn(w);
}

// ---------------- layer0 aggregation: gather x (cols 128-255), write agg cols 0-127 ----------------
__global__ void agg0_kernel() {
    int gw   = (blockIdx.x * blockDim.x + threadIdx.x) >> 5;
    int lane = threadIdx.x & 31;
    if (gw >= N_NODES) return;
    int beg = g_rowptr[gw];
    int end = g_rowptr[gw + 1];

    float a[4] = {0.f, 0.f, 0.f, 0.f};
    float b[4] = {0.f, 0.f, 0.f, 0.f};
    int e = beg;
    for (; e + 1 < end; e += 2) {
        int s0 = g_col[e], s1 = g_col[e + 1];
        uint2 u0 = __ldg((const uint2*)(g_A + (size_t)s0 * 512 + 128) + lane);
        uint2 u1 = __ldg((const uint2*)(g_A + (size_t)s1 * 512 + 128) + lane);
        __half2 p0 = *reinterpret_cast<__half2*>(&u0.x);
        __half2 p1 = *reinterpret_cast<__half2*>(&u0.y);
        __half2 q0 = *reinterpret_cast<__half2*>(&u1.x);
        __half2 q1 = *reinterpret_cast<__half2*>(&u1.y);
        float2 f0 = __half22float2(p0), f1 = __half22float2(p1);
        float2 g0 = __half22float2(q0), g1 = __half22float2(q1);
        a[0] += f0.x; a[1] += f0.y; a[2] += f1.x; a[3] += f1.y;
        b[0] += g0.x; b[1] += g0.y; b[2] += g1.x; b[3] += g1.y;
    }
    if (e < end) {
        int s0 = g_col[e];
        uint2 u0 = __ldg((const uint2*)(g_A + (size_t)s0 * 512 + 128) + lane);
        __half2 p0 = *reinterpret_cast<__half2*>(&u0.x);
        __half2 p1 = *reinterpret_cast<__half2*>(&u0.y);
        float2 f0 = __half22float2(p0), f1 = __half22float2(p1);
        a[0] += f0.x; a[1] += f0.y; a[2] += f1.x; a[3] += f1.y;
    }
    float inv = 1.0f / fmaxf((float)(end - beg), 1.0f);
    __half2 o01 = __floats2half2_rn((a[0] + b[0]) * inv, (a[1] + b[1]) * inv);
    __half2 o23 = __floats2half2_rn((a[2] + b[2]) * inv, (a[3] + b[3]) * inv);
    uint2 u;
    u.x = *reinterpret_cast<uint32_t*>(&o01);
    u.y = *reinterpret_cast<uint32_t*>(&o23);
    *(uint2*)(g_A + (size_t)gw * 512 + lane * 4) = u;
}

// ---------------- layers 1/2 aggregation: gather root cols 256-511, write agg cols 0-255 ----------------
__global__ void agg_bf_kernel() {
    int gw   = (blockIdx.x * blockDim.x + threadIdx.x) >> 5;
    int lane = threadIdx.x & 31;
    if (gw >= N_NODES) return;
    int beg = g_rowptr[gw];
    int end = g_rowptr[gw + 1];

    float a[8] = {0.f, 0.f, 0.f, 0.f, 0.f, 0.f, 0.f, 0.f};
    float b[8] = {0.f, 0.f, 0.f, 0.f, 0.f, 0.f, 0.f, 0.f};
    int e = beg;
    for (; e + 1 < end; e += 2) {
        int s0 = g_col[e], s1 = g_col[e + 1];
        uint4 u = __ldg((const uint4*)(g_A + (size_t)s0 * 512 + 256) + lane);
        uint4 v = __ldg((const uint4*)(g_A + (size_t)s1 * 512 + 256) + lane);
        __half2 h0 = *reinterpret_cast<__half2*>(&u.x);
        __half2 h1 = *reinterpret_cast<__half2*>(&u.y);
        __half2 h2 = *reinterpret_cast<__half2*>(&u.z);
        __half2 h3 = *reinterpret_cast<__half2*>(&u.w);
        float2 f0 = __half22float2(h0), f1 = __half22float2(h1);
        float2 f2 = __half22float2(h2), f3 = __half22float2(h3);
        a[0] += f0.x; a[1] += f0.y; a[2] += f1.x; a[3] += f1.y;
        a[4] += f2.x; a[5] += f2.y; a[6] += f3.x; a[7] += f3.y;
        __half2 k0 = *reinterpret_cast<__half2*>(&v.x);
        __half2 k1 = *reinterpret_cast<__half2*>(&v.y);
        __half2 k2 = *reinterpret_cast<__half2*>(&v.z);
        __half2 k3 = *reinterpret_cast<__half2*>(&v.w);
        float2 g0 = __half22float2(k0), g1 = __half22float2(k1);
        float2 g2 = __half22float2(k2), g3 = __half22float2(k3);
        b[0] += g0.x; b[1] += g0.y; b[2] += g1.x; b[3] += g1.y;
        b[4] += g2.x; b[5] += g2.y; b[6] += g3.x; b[7] += g3.y;
    }
    if (e < end) {
        int s0 = g_col[e];
        uint4 u = __ldg((const uint4*)(g_A + (size_t)s0 * 512 + 256) + lane);
        __half2 h0 = *reinterpret_cast<__half2*>(&u.x);
        __half2 h1 = *reinterpret_cast<__half2*>(&u.y);
        __half2 h2 = *reinterpret_cast<__half2*>(&u.z);
        __half2 h3 = *reinterpret_cast<__half2*>(&u.w);
        float2 f0 = __half22float2(h0), f1 = __half22float2(h1);
        float2 f2 = __half22float2(h2), f3 = __half22float2(h3);
        a[0] += f0.x; a[1] += f0.y; a[2] += f1.x; a[3] += f1.y;
        a[4] += f2.x; a[5] += f2.y; a[6] += f3.x; a[7] += f3.y;
    }
    float inv = 1.0f / fmaxf((float)(end - beg), 1.0f);
    __half2 o0 = __floats2half2_rn((a[0] + b[0]) * inv, (a[1] + b[1]) * inv);
    __half2 o1 = __floats2half2_rn((a[2] + b[2]) * inv, (a[3] + b[3]) * inv);
    __half2 o2 = __floats2half2_rn((a[4] + b[4]) * inv, (a[5] + b[5]) * inv);
    __half2 o3 = __floats2half2_rn((a[6] + b[6]) * inv, (a[7] + b[7]) * inv);
    uint4 u;
    u.x = *reinterpret_cast<uint32_t*>(&o0);
    u.y = *reinterpret_cast<uint32_t*>(&o1);
    u.z = *reinterpret_cast<uint32_t*>(&o2);
    u.w = *reinterpret_cast<uint32_t*>(&o3);
    *(uint4*)(g_A + (size_t)gw * 512 + lane * 8) = u;
}

// ---------------- fp16 HMMA GEMM (R11 champion config), fused BN-stats epilogue ----------------
// CTA tile 128x128, 256 threads = 8 warps (4m x 2n), warp tile 32x64, K-chunk 32,
// double-buffered cp.async, grid (391, 2).
#define SA 40                        // smem halves per row (32 + 8 pad)
#define OF_B 10240u
#define BUFB 20480u
#define SM_GEMM (2 * 20480)

template <int KT>   // k-extent: 256 (layer0) or 512; row stride is always 512
__global__ void __launch_bounds__(256, 2)
hmma_gemm_kernel(const __half* __restrict__ A, const __half* __restrict__ B,
                 const float* __restrict__ bias, float* __restrict__ C,
                 float* __restrict__ stats) {
    extern __shared__ char smem[];
    const uint32_t sb = smem_u32(smem);
    const int tid  = threadIdx.x;
    const int lane = tid & 31;
    const int wid  = tid >> 5;
    const int wm   = wid & 3;
    const int wn   = wid >> 2;
    const int bm   = blockIdx.x * 128;
    const int bn   = blockIdx.y * 128;

    float acc[2][8][4];
#pragma unroll
    for (int a = 0; a < 2; a++)
#pragma unroll
        for (int b = 0; b < 8; b++)
#pragma unroll
            for (int c = 0; c < 4; c++) acc[a][b][c] = 0.0f;

    auto issue = [&](int buf, int k0) {
        uint32_t base = sb + buf * BUFB;
#pragma unroll
        for (int v = 0; v < 2; v++) {
            int idx = v * 256 + tid;         // 0..511
            int r = idx >> 2, s = idx & 3;
            int grow = bm + r;
            if (grow >= N_NODES) grow = N_NODES - 1;   // clamp; excluded in epilogue
            size_t goA = (size_t)grow * 512 + k0 + s * 8;
            size_t goB = (size_t)(bn + r) * 512 + k0 + s * 8;
            uint32_t d = base + (uint32_t)(r * SA + s * 8) * 2;
            cp16(d, A + goA);
            cp16(d + OF_B, B + goB);
        }
    };

    const int nch = KT / 32;
    issue(0, 0);
    cpa_commit();
    int buf = 0;
    for (int ch = 0; ch < nch; ch++) {
        if (ch + 1 < nch) {
            issue(buf ^ 1, (ch + 1) * 32);
            cpa_commit();
            cpa_wait<1>();
        } else {
            cpa_wait<0>();
        }
        __syncthreads();
        uint32_t base = sb + buf * BUFB;
#pragma unroll
        for (int ks = 0; ks < 2; ks++) {
            const int kc = ks * 16;
            uint32_t ah[2][4];
#pragma unroll
            for (int mt = 0; mt < 2; mt++) {
                int row = wm * 32 + mt * 16 + (lane & 15);
                int col = kc + ((lane >> 4) << 3);
                ldm_x4(ah[mt], base + (uint32_t)(row * SA + col) * 2);
            }
#pragma unroll
            for (int g = 0; g < 4; g++) {
                int nrow = wn * 64 + g * 16 + ((lane >> 4) << 3) + (lane & 7);
                int kcol = kc + (((lane >> 3) & 1) << 3);
                uint32_t bh4[4];
                ldm_x4(bh4, base + (uint32_t)(nrow * SA + kcol) * 2 + OF_B);
#pragma unroll
                for (int mt = 0; mt < 2; mt++)
#pragma unroll
                    for (int s = 0; s < 2; s++)
                        mma_fp16(acc[mt][g * 2 + s], ah[mt], &bh4[s * 2]);
            }
        }
        __syncthreads();
        buf ^= 1;
    }

    // ---- epilogue: write C (+bias) and fused BN column stats (float) ----
    float* ssum = (float*)smem;          // [128]
    float* ssq  = ssum + 128;            // [128]
    if (tid < 128) { ssum[tid] = 0.0f; ssq[tid] = 0.0f; }
    __syncthreads();

#pragma unroll
    for (int nt = 0; nt < 8; nt++) {
        int col = bn + wn * 64 + nt * 8 + (lane & 3) * 2;
        float b0 = __ldg(&bias[col]);
        float b1 = __ldg(&bias[col + 1]);
        float p0 = 0.f, p1 = 0.f, q0 = 0.f, q1 = 0.f;
#pragma unroll
        for (int mt = 0; mt < 2; mt++) {
            int row0 = bm + wm * 32 + mt * 16 + (lane >> 2);
            float c0 = acc[mt][nt][0] + b0;
            float c1 = acc[mt][nt][1] + b1;
            float c2 = acc[mt][nt][2] + b0;
            float c3 = acc[mt][nt][3] + b1;
            if (row0 < N_NODES) {
                C[(size_t)row0 * HID + col]     = c0;
                C[(size_t)row0 * HID + col + 1] = c1;
                p0 += c0; q0 += c0 * c0;
                p1 += c1; q1 += c1 * c1;
            }
            if (row0 + 8 < N_NODES) {
                C[(size_t)(row0 + 8) * HID + col]     = c2;
                C[(size_t)(row0 + 8) * HID + col + 1] = c3;
                p0 += c2; q0 += c2 * c2;
                p1 += c3; q1 += c3 * c3;
            }
        }
#pragma unroll
        for (int m = 4; m < 32; m <<= 1) {
            p0 += __shfl_xor_sync(0xFFFFFFFFu, p0, m);
            p1 += __shfl_xor_sync(0xFFFFFFFFu, p1, m);
            q0 += __shfl_xor_sync(0xFFFFFFFFu, q0, m);
            q1 += __shfl_xor_sync(0xFFFFFFFFu, q1, m);
        }
        if (lane < 4) {
            int lc = wn * 64 + nt * 8 + lane * 2;
            atomicAdd(&ssum[lc], p0);     atomicAdd(&ssq[lc], q0);
            atomicAdd(&ssum[lc + 1], p1); atomicAdd(&ssq[lc + 1], q1);
        }
    }
    __syncthreads();
    if (tid < 128) {
        int col = bn + tid;
        atomicAdd(&stats[col],       ssum[tid]);
        atomicAdd(&stats[256 + col], ssq[tid]);
    }
}

// ---------------- normalize + ELU ----------------
// write_mode: 0 = fp16 root cols of g_A (layers 0/1), 1 = fp32 out (final layer)
__global__ void norm_elu_kernel(const float* __restrict__ h,
                                const float* __restrict__ gamma,
                                const float* __restrict__ beta,
                                const float* __restrict__ stats,
                                float* __restrict__ out,
                                int write_mode) {
    __shared__ float sscale[HID];
    __shared__ float sshift[HID];
    int tid = threadIdx.x;   // 256
    {
        double mu  = (double)stats[tid] * (1.0 / N_NODES);
        double var = (double)stats[256 + tid] * (1.0 / N_NODES) - mu * mu;
        float sc = gamma[tid] * rsqrtf((float)var + BN_EPS);
        sscale[tid] = sc;
        sshift[tid] = beta[tid] - (float)mu * sc;
    }
    __syncthreads();
    int r0 = blockIdx.x * 64;
    int r1 = min(r0 + 64, N_NODES);
    float sc = sscale[tid];
    float sh = sshift[tid];
    for (int r = r0; r < r1; r++) {
        size_t idx = (size_t)r * HID + tid;
        float v = h[idx] * sc + sh;
        float o = (v > 0.0f) ? v : expm1f(v);
        if (write_mode == 1) {
            out[idx] = o;
        } else {
            g_A[(size_t)r * 512 + 256 + tid] = __float2half_rn(o);
        }
    }
}

// ---------------- launch ----------------
extern "C" void kernel_launch(void* const* d_in, const int* in_sizes, int n_in,
                              void* d_out, int out_size) {
    (void)in_sizes; (void)n_in; (void)out_size;
    const float* x  = (const float*)d_in[0];
    const int*   ei = (const int*)d_in[1];
    const float* Wn[3] = {(const float*)d_in[2], (const float*)d_in[7],  (const float*)d_in[12]};
    const float* bn[3] = {(const float*)d_in[3], (const float*)d_in[8],  (const float*)d_in[13]};
    const float* Wr[3] = {(const float*)d_in[4], (const float*)d_in[9],  (const float*)d_in[14]};
    const float* gg[3] = {(const float*)d_in[5], (const float*)d_in[10], (const float*)d_in[15]};
    const float* bb[3] = {(const float*)d_in[6], (const float*)d_in[11], (const float*)d_in[16]};
    float* out = (float*)d_out;

    float *h_p, *stats_p;
    __half *A_p, *B_p;
    cudaGetSymbolAddress((void**)&h_p,     g_h);
    cudaGetSymbolAddress((void**)&stats_p, g_stats);
    cudaGetSymbolAddress((void**)&A_p,     g_A);
    cudaGetSymbolAddress((void**)&B_p,     g_B);

    cudaFuncSetAttribute(hmma_gemm_kernel<256>, cudaFuncAttributeMaxDynamicSharedMemorySize, SM_GEMM);
    cudaFuncSetAttribute(hmma_gemm_kernel<512>, cudaFuncAttributeMaxDynamicSharedMemorySize, SM_GEMM);

    const int TB = 256;
    const int nb_nodes = (N_NODES + TB - 1) / TB;
    const int nb_edges = (N_EDGES + TB - 1) / TB;
    const int agg_blocks = (N_NODES * 32 + TB - 1) / TB;
    const int cx_blocks  = (N_NODES * 32 + TB - 1) / TB;
    const int cw_blocks  = (3 * HID * 512 + TB - 1) / TB;
    const int norm_blocks = (N_NODES + 63) / 64;
    dim3 gemm_grid((N_NODES + 127) / 128, 2);

    // ---- CSR build + zeroing + upfront converts ----
    prep_kernel<<<nb_nodes, TB>>>();
    count_kernel<<<nb_edges, TB>>>(ei);
    scan1_kernel<<<SCAN_NB, 1024>>>();
    scan2_kernel<<<1, 64>>>();
    scan3_kernel<<<SCAN_NB, 1024>>>();
    scatter_kernel<<<nb_edges, TB>>>(ei);
    convert_x_kernel<<<cx_blocks, TB>>>(x);
    convert_w_all_kernel<<<cw_blocks, TB>>>(Wn[0], Wr[0], Wn[1], Wr[1], Wn[2], Wr[2]);

    // ---- layer 0 (KEXT=256) ----
    agg0_kernel<<<agg_blocks, TB>>>();
    hmma_gemm_kernel<256><<<gemm_grid, 256, SM_GEMM>>>(A_p, B_p, bn[0], h_p, stats_p);
    norm_elu_kernel<<<norm_blocks, HID>>>(h_p, gg[0], bb[0], stats_p, nullptr, 0);

    // ---- layer 1 (KEXT=512) ----
    agg_bf_kernel<<<agg_blocks, TB>>>();
    hmma_gemm_kernel<512><<<gemm_grid, 256, SM_GEMM>>>(A_p, B_p + 131072, bn[1], h_p, stats_p + 512);
    norm_elu_kernel<<<norm_blocks, HID>>>(h_p, gg[1], bb[1], stats_p + 512, nullptr, 0);

    // ---- layer 2 (KEXT=512) ----
    agg_bf_kernel<<<agg_blocks, TB>>>();
    hmma_gemm_kernel<512><<<gemm_grid, 256, SM_GEMM>>>(A_p, B_p + 2 * 131072, bn[2], out, stats_p + 1024);
    norm_elu_kernel<<<norm_blocks, HID>>>(out, gg[2], bb[2], stats_p + 1024, out, 1);
}

// round 16
// speedup vs baseline: 1.6399x; 1.0326x over previous
#include <cuda_runtime.h>
#include <cuda_fp16.h>
#include <math.h>
#include <stdint.h>

#define N_NODES 50000
#define N_EDGES 800000
#define F_INDIM 128
#define HID 256
#define BN_EPS 1e-5f
#define SCAN_NB 49       // ceil(50000/1024)
#define NORM_BLOCKS 782  // ceil(50000/64)
#define CURSOR_BLOCKS 196

// ---------------- scratch (device globals: no allocation allowed) ----------------
// NOTE: g_cursor must be ZERO at entry to kernel_launch. It is zero at module load,
// and the tail blocks of the final norm_elu launch re-zero it for the next call.
__device__ int    g_rowptr[N_NODES + 1];
__device__ int    g_cursor[N_NODES];
__device__ int    g_bsum[64];
__device__ int    g_col[N_EDGES];
__device__ float  g_h[(size_t)N_NODES * HID];          // pre-BN activations (fp32)
__device__ __half g_A[(size_t)N_NODES * 512];          // fp16 A: cols[0:256)=agg, [256:512)=root/gather
__device__ __half g_B[3 * (size_t)HID * 512];          // fp16 B per layer = [Wn;Wr]^T, row stride 512
__device__ float  g_stats[3 * 512];                    // per layer: [0:256)=sum, [256:512)=sumsq

// ---------------- small helpers ----------------
__device__ __forceinline__ uint32_t smem_u32(const void* p) {
    uint32_t a;
    asm("{ .reg .u64 t; cvta.to.shared.u64 t, %1; cvt.u32.u64 %0, t; }" : "=r"(a) : "l"(p));
    return a;
}
__device__ __forceinline__ void cp16(uint32_t dst, const void* src) {
    asm volatile("cp.async.cg.shared.global [%0], [%1], 16;" :: "r"(dst), "l"(src) : "memory");
}
__device__ __forceinline__ void cpa_commit() {
    asm volatile("cp.async.commit_group;" ::: "memory");
}
template <int NN>
__device__ __forceinline__ void cpa_wait() {
    asm volatile("cp.async.wait_group %0;" :: "n"(NN) : "memory");
}
__device__ __forceinline__ void ldm_x4(uint32_t* r, uint32_t addr) {
    asm volatile("ldmatrix.sync.aligned.m8n8.x4.shared.b16 {%0,%1,%2,%3}, [%4];"
                 : "=r"(r[0]), "=r"(r[1]), "=r"(r[2]), "=r"(r[3]) : "r"(addr));
}
__device__ __forceinline__ void mma_fp16(float* d, const uint32_t* a, const uint32_t* b) {
    asm volatile("mma.sync.aligned.m16n8k16.row.col.f32.f16.f16.f32 "
                 "{%0,%1,%2,%3}, {%4,%5,%6,%7}, {%8,%9}, {%0,%1,%2,%3};"
                 : "+f"(d[0]), "+f"(d[1]), "+f"(d[2]), "+f"(d[3])
                 : "r"(a[0]), "r"(a[1]), "r"(a[2]), "r"(a[3]), "r"(b[0]), "r"(b[1]));
}

// ---------------- fused setup: count + convert_x + convert_w + zero stats ----------------
// Block ranges (grid = 10917):
//   [0, 3125)        count: atomicAdd into g_cursor (pre-zeroed by previous call / boot)
//   [3125, 9375)     convert_x -> fp16 root cols A[:,128:256)
//   [9375, 10911)    convert all 3 layers' weights
//   [10911, 10917)   zero 3*512 stats
__global__ void setup_kernel(const int* __restrict__ ei, const float* __restrict__ x,
                             const float* __restrict__ Wn0, const float* __restrict__ Wr0,
                             const float* __restrict__ Wn1, const float* __restrict__ Wr1,
                             const float* __restrict__ Wn2, const float* __restrict__ Wr2) {
    int b = blockIdx.x;
    int tid = threadIdx.x;
    if (b < 3125) {
        int e = b * 256 + tid;
        if (e < N_EDGES) atomicAdd(&g_cursor[ei[N_EDGES + e]], 1);
    } else if (b < 9375) {
        int i = (b - 3125) * 256 + tid;          // over N*32 = 1.6M exactly
        int row = i >> 5, grp = i & 31;
        const float4 v = __ldg((const float4*)(x + (size_t)row * 128 + grp * 4));
        __half2 h01 = __floats2half2_rn(v.x, v.y);
        __half2 h23 = __floats2half2_rn(v.z, v.w);
        uint2 u;
        u.x = *reinterpret_cast<uint32_t*>(&h01);
        u.y = *reinterpret_cast<uint32_t*>(&h23);
        *(uint2*)(g_A + (size_t)row * 512 + 128 + grp * 4) = u;
    } else if (b < 10911) {
        int i = (b - 9375) * 256 + tid;          // over 3*256*512 = 393216 exactly
        int l = i >> 17;
        int j = i & 131071;
        int n = j >> 9;
        int k = j & 511;
        int DIN  = (l == 0) ? 128 : 256;
        int KEXT = (l == 0) ? 256 : 512;
        if (k < KEXT) {
            const float* Wn = (l == 0) ? Wn0 : (l == 1) ? Wn1 : Wn2;
            const float* Wr = (l == 0) ? Wr0 : (l == 1) ? Wr1 : Wr2;
            float w = (k < DIN) ? Wn[(size_t)k * HID + n] : Wr[(size_t)(k - DIN) * HID + n];
            g_B[(size_t)l * 131072 + (size_t)n * 512 + k] = __float2half_rn(w);
        }
    } else {
        int i = (b - 10911) * 256 + tid;
        if (i < 3 * 512) g_stats[i] = 0.0f;
    }
}

// ---- multi-block scan: phase 1 ----
__global__ void scan1_kernel() {
    __shared__ int sh[1024];
    int tid = threadIdx.x;
    int i = blockIdx.x * 1024 + tid;
    int v = (i < N_NODES) ? g_cursor[i] : 0;
    sh[tid] = v;
    __syncthreads();
    for (int off = 1; off < 1024; off <<= 1) {
        int t = (tid >= off) ? sh[tid - off] : 0;
        __syncthreads();
        sh[tid] += t;
        __syncthreads();
    }
    if (i < N_NODES) g_rowptr[i] = sh[tid] - v;
    if (tid == 1023) g_bsum[blockIdx.x] = sh[1023];
}
// ---- phase 2 ----
__global__ void scan2_kernel() {
    __shared__ int sh[64];
    int tid = threadIdx.x;
    int v = (tid < SCAN_NB) ? g_bsum[tid] : 0;
    sh[tid] = v;
    __syncthreads();
    for (int off = 1; off < 64; off <<= 1) {
        int t = (tid >= off) ? sh[tid - off] : 0;
        __syncthreads();
        sh[tid] += t;
        __syncthreads();
    }
    if (tid < SCAN_NB) g_bsum[tid] = sh[tid] - v;
    if (tid == 63) g_rowptr[N_NODES] = sh[63];
}
// ---- phase 3: add block offsets, init cursor ----
__global__ void scan3_kernel() {
    int i = blockIdx.x * 1024 + threadIdx.x;
    if (i < N_NODES) {
        int r = g_rowptr[i] + g_bsum[blockIdx.x];
        g_rowptr[i] = r;
        g_cursor[i] = r;
    }
}
__global__ void scatter_kernel(const int* __restrict__ ei) {
    int e = blockIdx.x * blockDim.x + threadIdx.x;
    if (e < N_EDGES) {
        int s = ei[e];
        int d = ei[N_EDGES + e];
        g_col[atomicAdd(&g_cursor[d], 1)] = s;
    }
}

// ---------------- layer0 aggregation: gather x (cols 128-255), write agg cols 0-127 ----------------
__global__ void agg0_kernel() {
    int gw   = (blockIdx.x * blockDim.x + threadIdx.x) >> 5;
    int lane = threadIdx.x & 31;
    if (gw >= N_NODES) return;
    int beg = g_rowptr[gw];
    int end = g_rowptr[gw + 1];

    float a[4] = {0.f, 0.f, 0.f, 0.f};
    float b[4] = {0.f, 0.f, 0.f, 0.f};
    int e = beg;
    for (; e + 1 < end; e += 2) {
        int s0 = g_col[e], s1 = g_col[e + 1];
        uint2 u0 = __ldg((const uint2*)(g_A + (size_t)s0 * 512 + 128) + lane);
        uint2 u1 = __ldg((const uint2*)(g_A + (size_t)s1 * 512 + 128) + lane);
        __half2 p0 = *reinterpret_cast<__half2*>(&u0.x);
        __half2 p1 = *reinterpret_cast<__half2*>(&u0.y);
        __half2 q0 = *reinterpret_cast<__half2*>(&u1.x);
        __half2 q1 = *reinterpret_cast<__half2*>(&u1.y);
        float2 f0 = __half22float2(p0), f1 = __half22float2(p1);
        float2 g0 = __half22float2(q0), g1 = __half22float2(q1);
        a[0] += f0.x; a[1] += f0.y; a[2] += f1.x; a[3] += f1.y;
        b[0] += g0.x; b[1] += g0.y; b[2] += g1.x; b[3] += g1.y;
    }
    if (e < end) {
        int s0 = g_col[e];
        uint2 u0 = __ldg((const uint2*)(g_A + (size_t)s0 * 512 + 128) + lane);
        __half2 p0 = *reinterpret_cast<__half2*>(&u0.x);
        __half2 p1 = *reinterpret_cast<__half2*>(&u0.y);
        float2 f0 = __half22float2(p0), f1 = __half22float2(p1);
        a[0] += f0.x; a[1] += f0.y; a[2] += f1.x; a[3] += f1.y;
    }
    float inv = 1.0f / fmaxf((float)(end - beg), 1.0f);
    __half2 o01 = __floats2half2_rn((a[0] + b[0]) * inv, (a[1] + b[1]) * inv);
    __half2 o23 = __floats2half2_rn((a[2] + b[2]) * inv, (a[3] + b[3]) * inv);
    uint2 u;
    u.x = *reinterpret_cast<uint32_t*>(&o01);
    u.y = *reinterpret_cast<uint32_t*>(&o23);
    *(uint2*)(g_A + (size_t)gw * 512 + lane * 4) = u;
}

// ---------------- layers 1/2 aggregation: gather root cols 256-511, write agg cols 0-255 ----------------
__global__ void agg_bf_kernel() {
    int gw   = (blockIdx.x * blockDim.x + threadIdx.x) >> 5;
    int lane = threadIdx.x & 31;
    if (gw >= N_NODES) return;
    int beg = g_rowptr[gw];
    int end = g_rowptr[gw + 1];

    float a[8] = {0.f, 0.f, 0.f, 0.f, 0.f, 0.f, 0.f, 0.f};
    float b[8] = {0.f, 0.f, 0.f, 0.f, 0.f, 0.f, 0.f, 0.f};
    int e = beg;
    for (; e + 1 < end; e += 2) {
        int s0 = g_col[e], s1 = g_col[e + 1];
        uint4 u = __ldg((const uint4*)(g_A + (size_t)s0 * 512 + 256) + lane);
        uint4 v = __ldg((const uint4*)(g_A + (size_t)s1 * 512 + 256) + lane);
        __half2 h0 = *reinterpret_cast<__half2*>(&u.x);
        __half2 h1 = *reinterpret_cast<__half2*>(&u.y);
        __half2 h2 = *reinterpret_cast<__half2*>(&u.z);
        __half2 h3 = *reinterpret_cast<__half2*>(&u.w);
        float2 f0 = __half22float2(h0), f1 = __half22float2(h1);
        float2 f2 = __half22float2(h2), f3 = __half22float2(h3);
        a[0] += f0.x; a[1] += f0.y; a[2] += f1.x; a[3] += f1.y;
        a[4] += f2.x; a[5] += f2.y; a[6] += f3.x; a[7] += f3.y;
        __half2 k0 = *reinterpret_cast<__half2*>(&v.x);
        __half2 k1 = *reinterpret_cast<__half2*>(&v.y);
        __half2 k2 = *reinterpret_cast<__half2*>(&v.z);
        __half2 k3 = *reinterpret_cast<__half2*>(&v.w);
        float2 g0 = __half22float2(k0), g1 = __half22float2(k1);
        float2 g2 = __half22float2(k2), g3 = __half22float2(k3);
        b[0] += g0.x; b[1] += g0.y; b[2] += g1.x; b[3] += g1.y;
        b[4] += g2.x; b[5] += g2.y; b[6] += g3.x; b[7] += g3.y;
    }
    if (e < end) {
        int s0 = g_col[e];
        uint4 u = __ldg((const uint4*)(g_A + (size_t)s0 * 512 + 256) + lane);
        __half2 h0 = *reinterpret_cast<__half2*>(&u.x);
        __half2 h1 = *reinterpret_cast<__half2*>(&u.y);
        __half2 h2 = *reinterpret_cast<__half2*>(&u.z);
        __half2 h3 = *reinterpret_cast<__half2*>(&u.w);
        float2 f0 = __half22float2(h0), f1 = __half22float2(h1);
        float2 f2 = __half22float2(h2), f3 = __half22float2(h3);
        a[0] += f0.x; a[1] += f0.y; a[2] += f1.x; a[3] += f1.y;
        a[4] += f2.x; a[5] += f2.y; a[6] += f3.x; a[7] += f3.y;
    }
    float inv = 1.0f / fmaxf((float)(end - beg), 1.0f);
    __half2 o0 = __floats2half2_rn((a[0] + b[0]) * inv, (a[1] + b[1]) * inv);
    __half2 o1 = __floats2half2_rn((a[2] + b[2]) * inv, (a[3] + b[3]) * inv);
    __half2 o2 = __floats2half2_rn((a[4] + b[4]) * inv, (a[5] + b[5]) * inv);
    __half2 o3 = __floats2half2_rn((a[6] + b[6]) * inv, (a[7] + b[7]) * inv);
    uint4 u;
    u.x = *reinterpret_cast<uint32_t*>(&o0);
    u.y = *reinterpret_cast<uint32_t*>(&o1);
    u.z = *reinterpret_cast<uint32_t*>(&o2);
    u.w = *reinterpret_cast<uint32_t*>(&o3);
    *(uint4*)(g_A + (size_t)gw * 512 + lane * 8) = u;
}

// ---------------- fp16 HMMA GEMM (champion config), fused BN-stats epilogue ----------------
// CTA tile 128x128, 256 threads = 8 warps (4m x 2n), warp tile 32x64, K-chunk 32,
// double-buffered cp.async, grid (391, 2).
#define SA 40                        // smem halves per row (32 + 8 pad)
#define OF_B 10240u
#define BUFB 20480u
#define SM_GEMM (2 * 20480)

template <int KT>   // k-extent: 256 (layer0) or 512; row stride is always 512
__global__ void __launch_bounds__(256, 2)
hmma_gemm_kernel(const __half* __restrict__ A, const __half* __restrict__ B,
                 const float* __restrict__ bias, float* __restrict__ C,
                 float* __restrict__ stats) {
    extern __shared__ char smem[];
    const uint32_t sb = smem_u32(smem);
    const int tid  = threadIdx.x;
    const int lane = tid & 31;
    const int wid  = tid >> 5;
    const int wm   = wid & 3;
    const int wn   = wid >> 2;
    const int bm   = blockIdx.x * 128;
    const int bn   = blockIdx.y * 128;

    float acc[2][8][4];
#pragma unroll
    for (int a = 0; a < 2; a++)
#pragma unroll
        for (int b = 0; b < 8; b++)
#pragma unroll
            for (int c = 0; c < 4; c++) acc[a][b][c] = 0.0f;

    auto issue = [&](int buf, int k0) {
        uint32_t base = sb + buf * BUFB;
#pragma unroll
        for (int v = 0; v < 2; v++) {
            int idx = v * 256 + tid;         // 0..511
            int r = idx >> 2, s = idx & 3;
            int grow = bm + r;
            if (grow >= N_NODES) grow = N_NODES - 1;   // clamp; excluded in epilogue
            size_t goA = (size_t)grow * 512 + k0 + s * 8;
            size_t goB = (size_t)(bn + r) * 512 + k0 + s * 8;
            uint32_t d = base + (uint32_t)(r * SA + s * 8) * 2;
            cp16(d, A + goA);
            cp16(d + OF_B, B + goB);
        }
    };

    const int nch = KT / 32;
    issue(0, 0);
    cpa_commit();
    int buf = 0;
    for (int ch = 0; ch < nch; ch++) {
        if (ch + 1 < nch) {
            issue(buf ^ 1, (ch + 1) * 32);
            cpa_commit();
            cpa_wait<1>();
        } else {
            cpa_wait<0>();
        }
        __syncthreads();
        uint32_t base = sb + buf * BUFB;
#pragma unroll
        for (int ks = 0; ks < 2; ks++) {
            const int kc = ks * 16;
            uint32_t ah[2][4];
#pragma unroll
            for (int mt = 0; mt < 2; mt++) {
                int row = wm * 32 + mt * 16 + (lane & 15);
                int col = kc + ((lane >> 4) << 3);
                ldm_x4(ah[mt], base + (uint32_t)(row * SA + col) * 2);
            }
#pragma unroll
            for (int g = 0; g < 4; g++) {
                int nrow = wn * 64 + g * 16 + ((lane >> 4) << 3) + (lane & 7);
                int kcol = kc + (((lane >> 3) & 1) << 3);
                uint32_t bh4[4];
                ldm_x4(bh4, base + (uint32_t)(nrow * SA + kcol) * 2 + OF_B);
#pragma unroll
                for (int mt = 0; mt < 2; mt++)
#pragma unroll
                    for (int s = 0; s < 2; s++)
                        mma_fp16(acc[mt][g * 2 + s], ah[mt], &bh4[s * 2]);
            }
        }
        __syncthreads();
        buf ^= 1;
    }

    // ---- epilogue: write C (+bias) and fused BN column stats (float) ----
    float* ssum = (float*)smem;          // [128]
    float* ssq  = ssum + 128;            // [128]
    if (tid < 128) { ssum[tid] = 0.0f; ssq[tid] = 0.0f; }
    __syncthreads();

#pragma unroll
    for (int nt = 0; nt < 8; nt++) {
        int col = bn + wn * 64 + nt * 8 + (lane & 3) * 2;
        float b0 = __ldg(&bias[col]);
        float b1 = __ldg(&bias[col + 1]);
        float p0 = 0.f, p1 = 0.f, q0 = 0.f, q1 = 0.f;
#pragma unroll
        for (int mt = 0; mt < 2; mt++) {
            int row0 = bm + wm * 32 + mt * 16 + (lane >> 2);
            float c0 = acc[mt][nt][0] + b0;
            float c1 = acc[mt][nt][1] + b1;
            float c2 = acc[mt][nt][2] + b0;
            float c3 = acc[mt][nt][3] + b1;
            if (row0 < N_NODES) {
                C[(size_t)row0 * HID + col]     = c0;
                C[(size_t)row0 * HID + col + 1] = c1;
                p0 += c0; q0 += c0 * c0;
                p1 += c1; q1 += c1 * c1;
            }
            if (row0 + 8 < N_NODES) {
                C[(size_t)(row0 + 8) * HID + col]     = c2;
                C[(size_t)(row0 + 8) * HID + col + 1] = c3;
                p0 += c2; q0 += c2 * c2;
                p1 += c3; q1 += c3 * c3;
            }
        }
#pragma unroll
        for (int m = 4; m < 32; m <<= 1) {
            p0 += __shfl_xor_sync(0xFFFFFFFFu, p0, m);
            p1 += __shfl_xor_sync(0xFFFFFFFFu, p1, m);
            q0 += __shfl_xor_sync(0xFFFFFFFFu, q0, m);
            q1 += __shfl_xor_sync(0xFFFFFFFFu, q1, m);
        }
        if (lane < 4) {
            int lc = wn * 64 + nt * 8 + lane * 2;
            atomicAdd(&ssum[lc], p0);     atomicAdd(&ssq[lc], q0);
            atomicAdd(&ssum[lc + 1], p1); atomicAdd(&ssq[lc + 1], q1);
        }
    }
    __syncthreads();
    if (tid < 128) {
        int col = bn + tid;
        atomicAdd(&stats[col],       ssum[tid]);
        atomicAdd(&stats[256 + col], ssq[tid]);
    }
}

// ---------------- normalize + ELU ----------------
// write_mode: 0 = fp16 root cols of g_A (layers 0/1), 1 = fp32 out (final layer)
// Final-layer launch carries CURSOR_BLOCKS extra tail blocks that zero g_cursor
// for the NEXT kernel_launch call (keeps prep off the critical path).
__global__ void norm_elu_kernel(const float* __restrict__ h,
                                const float* __restrict__ gamma,
                                const float* __restrict__ beta,
                                const float* __restrict__ stats,
                                float* __restrict__ out,
                                int write_mode) {
    int tid = threadIdx.x;   // 256
    if (blockIdx.x >= NORM_BLOCKS) {
        int i = (blockIdx.x - NORM_BLOCKS) * 256 + tid;
        if (i < N_NODES) g_cursor[i] = 0;
        return;
    }
    __shared__ float sscale[HID];
    __shared__ float sshift[HID];
    {
        double mu  = (double)stats[tid] * (1.0 / N_NODES);
        double var = (double)stats[256 + tid] * (1.0 / N_NODES) - mu * mu;
        float sc = gamma[tid] * rsqrtf((float)var + BN_EPS);
        sscale[tid] = sc;
        sshift[tid] = beta[tid] - (float)mu * sc;
    }
    __syncthreads();
    int r0 = blockIdx.x * 64;
    int r1 = min(r0 + 64, N_NODES);
    float sc = sscale[tid];
    float sh = sshift[tid];
    for (int r = r0; r < r1; r++) {
        size_t idx = (size_t)r * HID + tid;
        float v = h[idx] * sc + sh;
        float o = (v > 0.0f) ? v : expm1f(v);
        if (write_mode == 1) {
            out[idx] = o;
        } else {
            g_A[(size_t)r * 512 + 256 + tid] = __float2half_rn(o);
        }
    }
}

// ---------------- launch ----------------
extern "C" void kernel_launch(void* const* d_in, const int* in_sizes, int n_in,
                              void* d_out, int out_size) {
    (void)in_sizes; (void)n_in; (void)out_size;
    const float* x  = (const float*)d_in[0];
    const int*   ei = (const int*)d_in[1];
    const float* Wn[3] = {(const float*)d_in[2], (const float*)d_in[7],  (const float*)d_in[12]};
    const float* bn[3] = {(const float*)d_in[3], (const float*)d_in[8],  (const float*)d_in[13]};
    const float* Wr[3] = {(const float*)d_in[4], (const float*)d_in[9],  (const float*)d_in[14]};
    const float* gg[3] = {(const float*)d_in[5], (const float*)d_in[10], (const float*)d_in[15]};
    const float* bb[3] = {(const float*)d_in[6], (const float*)d_in[11], (const float*)d_in[16]};
    float* out = (float*)d_out;

    float *h_p, *stats_p;
    __half *A_p, *B_p;
    cudaGetSymbolAddress((void**)&h_p,     g_h);
    cudaGetSymbolAddress((void**)&stats_p, g_stats);
    cudaGetSymbolAddress((void**)&A_p,     g_A);
    cudaGetSymbolAddress((void**)&B_p,     g_B);

    cudaFuncSetAttribute(hmma_gemm_kernel<256>, cudaFuncAttributeMaxDynamicSharedMemorySize, SM_GEMM);
    cudaFuncSetAttribute(hmma_gemm_kernel<512>, cudaFuncAttributeMaxDynamicSharedMemorySize, SM_GEMM);

    const int TB = 256;
    const int nb_edges = (N_EDGES + TB - 1) / TB;
    const int agg_blocks = (N_NODES * 32 + TB - 1) / TB;
    dim3 gemm_grid((N_NODES + 127) / 128, 2);
    const int setup_blocks = 3125 + 6250 + 1536 + 6;   // count | convert_x | convert_w | stats

    // ---- fused setup (count + converts + stats-zero; cursor pre-zeroed by prior call) ----
    setup_kernel<<<setup_blocks, TB>>>(ei, x, Wn[0], Wr[0], Wn[1], Wr[1], Wn[2], Wr[2]);
    scan1_kernel<<<SCAN_NB, 1024>>>();
    scan2_kernel<<<1, 64>>>();
    scan3_kernel<<<SCAN_NB, 1024>>>();
    scatter_kernel<<<nb_edges, TB>>>(ei);

    // ---- layer 0 (KEXT=256) ----
    agg0_kernel<<<agg_blocks, TB>>>();
    hmma_gemm_kernel<256><<<gemm_grid, 256, SM_GEMM>>>(A_p, B_p, bn[0], h_p, stats_p);
    norm_elu_kernel<<<NORM_BLOCKS, HID>>>(h_p, gg[0], bb[0], stats_p, nullptr, 0);

    // ---- layer 1 (KEXT=512) ----
    agg_bf_kernel<<<agg_blocks, TB>>>();
    hmma_gemm_kernel<512><<<gemm_grid, 256, SM_GEMM>>>(A_p, B_p + 131072, bn[1], h_p, stats_p + 512);
    norm_elu_kernel<<<NORM_BLOCKS, HID>>>(h_p, gg[1], bb[1], stats_p + 512, nullptr, 0);

    // ---- layer 2 (KEXT=512) + tail blocks re-zero g_cursor for next call ----
    agg_bf_kernel<<<agg_blocks, TB>>>();
    hmma_gemm_kernel<512><<<gemm_grid, 256, SM_GEMM>>>(A_p, B_p + 2 * 131072, bn[2], out, stats_p + 1024);
    norm_elu_kernel<<<NORM_BLOCKS + CURSOR_BLOCKS, HID>>>(out, gg[2], bb[2], stats_p + 1024, out, 1);
}

// round 17
// speedup vs baseline: 1.7222x; 1.0502x over previous
#include <cuda_runtime.h>
#include <cuda_fp16.h>
#include <math.h>
#include <stdint.h>

#define N_NODES 50000
#define N_EDGES 800000
#define F_INDIM 128
#define HID 256
#define BN_EPS 1e-5f
#define SCAN_NB 49       // ceil(50000/1024)
#define NORM_BLOCKS 782  // ceil(50000/64)
#define CURSOR_BLOCKS 196

// ---------------- scratch (device globals: no allocation allowed) ----------------
// NOTE: g_cursor must be ZERO at entry to kernel_launch. It is zero at module load,
// and the tail blocks of the final norm_elu launch re-zero it for the next call.
__device__ int    g_rowptr[N_NODES + 1];
__device__ int    g_cursor[N_NODES];
__device__ int    g_bsum[64];
__device__ int    g_col[N_EDGES];
__device__ float  g_h[(size_t)N_NODES * HID];          // pre-BN activations (fp32)
__device__ __half g_A[(size_t)N_NODES * 512];          // fp16 A: cols[0:256)=agg, [256:512)=root/gather
__device__ __half g_B[3 * (size_t)HID * 512];          // fp16 B per layer = [Wn;Wr]^T, row stride 512
__device__ float  g_stats[3 * 512];                    // per layer: [0:256)=sum, [256:512)=sumsq

// ---------------- small helpers ----------------
__device__ __forceinline__ uint32_t smem_u32(const void* p) {
    uint32_t a;
    asm("{ .reg .u64 t; cvta.to.shared.u64 t, %1; cvt.u32.u64 %0, t; }" : "=r"(a) : "l"(p));
    return a;
}
__device__ __forceinline__ void cp16(uint32_t dst, const void* src) {
    asm volatile("cp.async.cg.shared.global [%0], [%1], 16;" :: "r"(dst), "l"(src) : "memory");
}
__device__ __forceinline__ void cpa_commit() {
    asm volatile("cp.async.commit_group;" ::: "memory");
}
template <int NN>
__device__ __forceinline__ void cpa_wait() {
    asm volatile("cp.async.wait_group %0;" :: "n"(NN) : "memory");
}
__device__ __forceinline__ void ldm_x4(uint32_t* r, uint32_t addr) {
    asm volatile("ldmatrix.sync.aligned.m8n8.x4.shared.b16 {%0,%1,%2,%3}, [%4];"
                 : "=r"(r[0]), "=r"(r[1]), "=r"(r[2]), "=r"(r[3]) : "r"(addr));
}
__device__ __forceinline__ void mma_fp16(float* d, const uint32_t* a, const uint32_t* b) {
    asm volatile("mma.sync.aligned.m16n8k16.row.col.f32.f16.f16.f32 "
                 "{%0,%1,%2,%3}, {%4,%5,%6,%7}, {%8,%9}, {%0,%1,%2,%3};"
                 : "+f"(d[0]), "+f"(d[1]), "+f"(d[2]), "+f"(d[3])
                 : "r"(a[0]), "r"(a[1]), "r"(a[2]), "r"(a[3]), "r"(b[0]), "r"(b[1]));
}

// ---------------- fused setup: count + convert_x + convert_w + zero stats ----------------
// Block ranges (grid = 10917):
//   [0, 3125)        count: atomicAdd into g_cursor (pre-zeroed by previous call / boot)
//   [3125, 9375)     convert_x -> fp16 root cols A[:,128:256)
//   [9375, 10911)    convert all 3 layers' weights
//   [10911, 10917)   zero 3*512 stats
__global__ void setup_kernel(const int* __restrict__ ei, const float* __restrict__ x,
                             const float* __restrict__ Wn0, const float* __restrict__ Wr0,
                             const float* __restrict__ Wn1, const float* __restrict__ Wr1,
                             const float* __restrict__ Wn2, const float* __restrict__ Wr2) {
    int b = blockIdx.x;
    int tid = threadIdx.x;
    if (b < 3125) {
        int e = b * 256 + tid;
        if (e < N_EDGES) atomicAdd(&g_cursor[ei[N_EDGES + e]], 1);
    } else if (b < 9375) {
        int i = (b - 3125) * 256 + tid;          // over N*32 = 1.6M exactly
        int row = i >> 5, grp = i & 31;
        const float4 v = __ldg((const float4*)(x + (size_t)row * 128 + grp * 4));
        __half2 h01 = __floats2half2_rn(v.x, v.y);
        __half2 h23 = __floats2half2_rn(v.z, v.w);
        uint2 u;
        u.x = *reinterpret_cast<uint32_t*>(&h01);
        u.y = *reinterpret_cast<uint32_t*>(&h23);
        *(uint2*)(g_A + (size_t)row * 512 + 128 + grp * 4) = u;
    } else if (b < 10911) {
        int i = (b - 9375) * 256 + tid;          // over 3*256*512 = 393216 exactly
        int l = i >> 17;
        int j = i & 131071;
        int n = j >> 9;
        int k = j & 511;
        int DIN  = (l == 0) ? 128 : 256;
        int KEXT = (l == 0) ? 256 : 512;
        if (k < KEXT) {
            const float* Wn = (l == 0) ? Wn0 : (l == 1) ? Wn1 : Wn2;
            const float* Wr = (l == 0) ? Wr0 : (l == 1) ? Wr1 : Wr2;
            float w = (k < DIN) ? Wn[(size_t)k * HID + n] : Wr[(size_t)(k - DIN) * HID + n];
            g_B[(size_t)l * 131072 + (size_t)n * 512 + k] = __float2half_rn(w);
        }
    } else {
        int i = (b - 10911) * 256 + tid;
        if (i < 3 * 512) g_stats[i] = 0.0f;
    }
}

// ---- multi-block scan: phase 1 (per-block exclusive scan + block sums) ----
__global__ void scan1_kernel() {
    __shared__ int sh[1024];
    int tid = threadIdx.x;
    int i = blockIdx.x * 1024 + tid;
    int v = (i < N_NODES) ? g_cursor[i] : 0;
    sh[tid] = v;
    __syncthreads();
    for (int off = 1; off < 1024; off <<= 1) {
        int t = (tid >= off) ? sh[tid - off] : 0;
        __syncthreads();
        sh[tid] += t;
        __syncthreads();
    }
    if (i < N_NODES) g_rowptr[i] = sh[tid] - v;
    if (tid == 1023) g_bsum[blockIdx.x] = sh[1023];
}
// ---- fused phase 2+3: each block computes its own offset from the 49 block sums ----
__global__ void scan23_kernel() {
    __shared__ int sbs[SCAN_NB];
    __shared__ int soff;
    int tid = threadIdx.x;
    if (tid < SCAN_NB) sbs[tid] = g_bsum[tid];
    __syncthreads();
    if (tid == 0) {
        int off = 0;
#pragma unroll
        for (int j = 0; j < SCAN_NB; j++) off += (j < blockIdx.x) ? sbs[j] : 0;
        soff = off;
        if (blockIdx.x == 0) g_rowptr[N_NODES] = N_EDGES;  // total degree = edge count
    }
    __syncthreads();
    int i = blockIdx.x * 1024 + tid;
    if (i < N_NODES) {
        int r = g_rowptr[i] + soff;
        g_rowptr[i] = r;
        g_cursor[i] = r;
    }
}
__global__ void scatter_kernel(const int* __restrict__ ei) {
    int e = blockIdx.x * blockDim.x + threadIdx.x;
    if (e < N_EDGES) {
        int s = ei[e];
        int d = ei[N_EDGES + e];
        g_col[atomicAdd(&g_cursor[d], 1)] = s;
    }
}

// ---------------- layer0 aggregation: gather x (cols 128-255), write agg cols 0-127 ----------------
__global__ void agg0_kernel() {
    int gw   = (blockIdx.x * blockDim.x + threadIdx.x) >> 5;
    int lane = threadIdx.x & 31;
    if (gw >= N_NODES) return;
    int beg = g_rowptr[gw];
    int end = g_rowptr[gw + 1];

    float a[4] = {0.f, 0.f, 0.f, 0.f};
    float b[4] = {0.f, 0.f, 0.f, 0.f};
    int e = beg;
    for (; e + 1 < end; e += 2) {
        int s0 = g_col[e], s1 = g_col[e + 1];
        uint2 u0 = __ldg((const uint2*)(g_A + (size_t)s0 * 512 + 128) + lane);
        uint2 u1 = __ldg((const uint2*)(g_A + (size_t)s1 * 512 + 128) + lane);
        __half2 p0 = *reinterpret_cast<__half2*>(&u0.x);
        __half2 p1 = *reinterpret_cast<__half2*>(&u0.y);
        __half2 q0 = *reinterpret_cast<__half2*>(&u1.x);
        __half2 q1 = *reinterpret_cast<__half2*>(&u1.y);
        float2 f0 = __half22float2(p0), f1 = __half22float2(p1);
        float2 g0 = __half22float2(q0), g1 = __half22float2(q1);
        a[0] += f0.x; a[1] += f0.y; a[2] += f1.x; a[3] += f1.y;
        b[0] += g0.x; b[1] += g0.y; b[2] += g1.x; b[3] += g1.y;
    }
    if (e < end) {
        int s0 = g_col[e];
        uint2 u0 = __ldg((const uint2*)(g_A + (size_t)s0 * 512 + 128) + lane);
        __half2 p0 = *reinterpret_cast<__half2*>(&u0.x);
        __half2 p1 = *reinterpret_cast<__half2*>(&u0.y);
        float2 f0 = __half22float2(p0), f1 = __half22float2(p1);
        a[0] += f0.x; a[1] += f0.y; a[2] += f1.x; a[3] += f1.y;
    }
    float inv = 1.0f / fmaxf((float)(end - beg), 1.0f);
    __half2 o01 = __floats2half2_rn((a[0] + b[0]) * inv, (a[1] + b[1]) * inv);
    __half2 o23 = __floats2half2_rn((a[2] + b[2]) * inv, (a[3] + b[3]) * inv);
    uint2 u;
    u.x = *reinterpret_cast<uint32_t*>(&o01);
    u.y = *reinterpret_cast<uint32_t*>(&o23);
    *(uint2*)(g_A + (size_t)gw * 512 + lane * 4) = u;
}

// ---------------- layers 1/2 aggregation: gather root cols 256-511, write agg cols 0-255 ----------------
__global__ void agg_bf_kernel() {
    int gw   = (blockIdx.x * blockDim.x + threadIdx.x) >> 5;
    int lane = threadIdx.x & 31;
    if (gw >= N_NODES) return;
    int beg = g_rowptr[gw];
    int end = g_rowptr[gw + 1];

    float a[8] = {0.f, 0.f, 0.f, 0.f, 0.f, 0.f, 0.f, 0.f};
    float b[8] = {0.f, 0.f, 0.f, 0.f, 0.f, 0.f, 0.f, 0.f};
    int e = beg;
    for (; e + 1 < end; e += 2) {
        int s0 = g_col[e], s1 = g_col[e + 1];
        uint4 u = __ldg((const uint4*)(g_A + (size_t)s0 * 512 + 256) + lane);
        uint4 v = __ldg((const uint4*)(g_A + (size_t)s1 * 512 + 256) + lane);
        __half2 h0 = *reinterpret_cast<__half2*>(&u.x);
        __half2 h1 = *reinterpret_cast<__half2*>(&u.y);
        __half2 h2 = *reinterpret_cast<__half2*>(&u.z);
        __half2 h3 = *reinterpret_cast<__half2*>(&u.w);
        float2 f0 = __half22float2(h0), f1 = __half22float2(h1);
        float2 f2 = __half22float2(h2), f3 = __half22float2(h3);
        a[0] += f0.x; a[1] += f0.y; a[2] += f1.x; a[3] += f1.y;
        a[4] += f2.x; a[5] += f2.y; a[6] += f3.x; a[7] += f3.y;
        __half2 k0 = *reinterpret_cast<__half2*>(&v.x);
        __half2 k1 = *reinterpret_cast<__half2*>(&v.y);
        __half2 k2 = *reinterpret_cast<__half2*>(&v.z);
        __half2 k3 = *reinterpret_cast<__half2*>(&v.w);
        float2 g0 = __half22float2(k0), g1 = __half22float2(k1);
        float2 g2 = __half22float2(k2), g3 = __half22float2(k3);
        b[0] += g0.x; b[1] += g0.y; b[2] += g1.x; b[3] += g1.y;
        b[4] += g2.x; b[5] += g2.y; b[6] += g3.x; b[7] += g3.y;
    }
    if (e < end) {
        int s0 = g_col[e];
        uint4 u = __ldg((const uint4*)(g_A + (size_t)s0 * 512 + 256) + lane);
        __half2 h0 = *reinterpret_cast<__half2*>(&u.x);
        __half2 h1 = *reinterpret_cast<__half2*>(&u.y);
        __half2 h2 = *reinterpret_cast<__half2*>(&u.z);
        __half2 h3 = *reinterpret_cast<__half2*>(&u.w);
        float2 f0 = __half22float2(h0), f1 = __half22float2(h1);
        float2 f2 = __half22float2(h2), f3 = __half22float2(h3);
        a[0] += f0.x; a[1] += f0.y; a[2] += f1.x; a[3] += f1.y;
        a[4] += f2.x; a[5] += f2.y; a[6] += f3.x; a[7] += f3.y;
    }
    float inv = 1.0f / fmaxf((float)(end - beg), 1.0f);
    __half2 o0 = __floats2half2_rn((a[0] + b[0]) * inv, (a[1] + b[1]) * inv);
    __half2 o1 = __floats2half2_rn((a[2] + b[2]) * inv, (a[3] + b[3]) * inv);
    __half2 o2 = __floats2half2_rn((a[4] + b[4]) * inv, (a[5] + b[5]) * inv);
    __half2 o3 = __floats2half2_rn((a[6] + b[6]) * inv, (a[7] + b[7]) * inv);
    uint4 u;
    u.x = *reinterpret_cast<uint32_t*>(&o0);
    u.y = *reinterpret_cast<uint32_t*>(&o1);
    u.z = *reinterpret_cast<uint32_t*>(&o2);
    u.w = *reinterpret_cast<uint32_t*>(&o3);
    *(uint4*)(g_A + (size_t)gw * 512 + lane * 8) = u;
}

// ---------------- fp16 HMMA GEMM, K-chunk 64, fused BN-stats epilogue ----------------
// CTA tile 128x128, 256 threads = 8 warps (4m x 2n), warp tile 32x64, K-chunk 64,
// double-buffered cp.async, grid (391, 2). 72KB smem, 2 CTAs/SM.
#define SA 72                        // smem halves per row (64 + 8 pad; 144B stride, ldmatrix conflict-free)
#define OF_B 18432u
#define BUFB 36864u
#define SM_GEMM (2 * 36864)

template <int KT>   // k-extent: 256 (layer0) or 512; row stride is always 512
__global__ void __launch_bounds__(256, 2)
hmma_gemm_kernel(const __half* __restrict__ A, const __half* __restrict__ B,
                 const float* __restrict__ bias, float* __restrict__ C,
                 float* __restrict__ stats) {
    extern __shared__ char smem[];
    const uint32_t sb = smem_u32(smem);
    const int tid  = threadIdx.x;
    const int lane = tid & 31;
    const int wid  = tid >> 5;
    const int wm   = wid & 3;
    const int wn   = wid >> 2;
    const int bm   = blockIdx.x * 128;
    const int bn   = blockIdx.y * 128;

    float acc[2][8][4];
#pragma unroll
    for (int a = 0; a < 2; a++)
#pragma unroll
        for (int b = 0; b < 8; b++)
#pragma unroll
            for (int c = 0; c < 4; c++) acc[a][b][c] = 0.0f;

    auto issue = [&](int buf, int k0) {
        uint32_t base = sb + buf * BUFB;
#pragma unroll
        for (int v = 0; v < 4; v++) {
            int idx = v * 256 + tid;         // 0..1023
            int r = idx >> 3, s = idx & 7;   // 128 rows x 8 sectors of 16B
            int grow = bm + r;
            if (grow >= N_NODES) grow = N_NODES - 1;   // clamp; excluded in epilogue
            size_t goA = (size_t)grow * 512 + k0 + s * 8;
            size_t goB = (size_t)(bn + r) * 512 + k0 + s * 8;
            uint32_t d = base + (uint32_t)(r * SA + s * 8) * 2;
            cp16(d, A + goA);
            cp16(d + OF_B, B + goB);
        }
    };

    const int nch = KT / 64;
    issue(0, 0);
    cpa_commit();
    int buf = 0;
    for (int ch = 0; ch < nch; ch++) {
        if (ch + 1 < nch) {
            issue(buf ^ 1, (ch + 1) * 64);
            cpa_commit();
            cpa_wait<1>();
        } else {
            cpa_wait<0>();
        }
        __syncthreads();
        uint32_t base = sb + buf * BUFB;
#pragma unroll
        for (int ks = 0; ks < 4; ks++) {
            const int kc = ks * 16;
            uint32_t ah[2][4];
#pragma unroll
            for (int mt = 0; mt < 2; mt++) {
                int row = wm * 32 + mt * 16 + (lane & 15);
                int col = kc + ((lane >> 4) << 3);
                ldm_x4(ah[mt], base + (uint32_t)(row * SA + col) * 2);
            }
#pragma unroll
            for (int g = 0; g < 4; g++) {
                int nrow = wn * 64 + g * 16 + ((lane >> 4) << 3) + (lane & 7);
                int kcol = kc + (((lane >> 3) & 1) << 3);
                uint32_t bh4[4];
                ldm_x4(bh4, base + (uint32_t)(nrow * SA + kcol) * 2 + OF_B);
#pragma unroll
                for (int mt = 0; mt < 2; mt++)
#pragma unroll
                    for (int s = 0; s < 2; s++)
                        mma_fp16(acc[mt][g * 2 + s], ah[mt], &bh4[s * 2]);
            }
        }
        __syncthreads();
        buf ^= 1;
    }

    // ---- epilogue: write C (+bias) and fused BN column stats (float) ----
    float* ssum = (float*)smem;          // [128]
    float* ssq  = ssum + 128;            // [128]
    if (tid < 128) { ssum[tid] = 0.0f; ssq[tid] = 0.0f; }
    __syncthreads();

#pragma unroll
    for (int nt = 0; nt < 8; nt++) {
        int col = bn + wn * 64 + nt * 8 + (lane & 3) * 2;
        float b0 = __ldg(&bias[col]);
        float b1 = __ldg(&bias[col + 1]);
        float p0 = 0.f, p1 = 0.f, q0 = 0.f, q1 = 0.f;
#pragma unroll
        for (int mt = 0; mt < 2; mt++) {
            int row0 = bm + wm * 32 + mt * 16 + (lane >> 2);
            float c0 = acc[mt][nt][0] + b0;
            float c1 = acc[mt][nt][1] + b1;
            float c2 = acc[mt][nt][2] + b0;
            float c3 = acc[mt][nt][3] + b1;
            if (row0 < N_NODES) {
                C[(size_t)row0 * HID + col]     = c0;
                C[(size_t)row0 * HID + col + 1] = c1;
                p0 += c0; q0 += c0 * c0;
                p1 += c1; q1 += c1 * c1;
            }
            if (row0 + 8 < N_NODES) {
                C[(size_t)(row0 + 8) * HID + col]     = c2;
                C[(size_t)(row0 + 8) * HID + col + 1] = c3;
                p0 += c2; q0 += c2 * c2;
                p1 += c3; q1 += c3 * c3;
            }
        }
#pragma unroll
        for (int m = 4; m < 32; m <<= 1) {
            p0 += __shfl_xor_sync(0xFFFFFFFFu, p0, m);
            p1 += __shfl_xor_sync(0xFFFFFFFFu, p1, m);
            q0 += __shfl_xor_sync(0xFFFFFFFFu, q0, m);
            q1 += __shfl_xor_sync(0xFFFFFFFFu, q1, m);
        }
        if (lane < 4) {
            int lc = wn * 64 + nt * 8 + lane * 2;
            atomicAdd(&ssum[lc], p0);     atomicAdd(&ssq[lc], q0);
            atomicAdd(&ssum[lc + 1], p1); atomicAdd(&ssq[lc + 1], q1);
        }
    }
    __syncthreads();
    if (tid < 128) {
        int col = bn + tid;
        atomicAdd(&stats[col],       ssum[tid]);
        atomicAdd(&stats[256 + col], ssq[tid]);
    }
}

// ---------------- normalize + ELU ----------------
// write_mode: 0 = fp16 root cols of g_A (layers 0/1), 1 = fp32 out (final layer)
// Final-layer launch carries CURSOR_BLOCKS extra tail blocks that zero g_cursor
// for the NEXT kernel_launch call (keeps prep off the critical path).
__global__ void norm_elu_kernel(const float* __restrict__ h,
                                const float* __restrict__ gamma,
                                const float* __restrict__ beta,
                                const float* __restrict__ stats,
                                float* __restrict__ out,
                                int write_mode) {
    int tid = threadIdx.x;   // 256
    if (blockIdx.x >= NORM_BLOCKS) {
        int i = (blockIdx.x - NORM_BLOCKS) * 256 + tid;
        if (i < N_NODES) g_cursor[i] = 0;
        return;
    }
    __shared__ float sscale[HID];
    __shared__ float sshift[HID];
    {
        double mu  = (double)stats[tid] * (1.0 / N_NODES);
        double var = (double)stats[256 + tid] * (1.0 / N_NODES) - mu * mu;
        float sc = gamma[tid] * rsqrtf((float)var + BN_EPS);
        sscale[tid] = sc;
        sshift[tid] = beta[tid] - (float)mu * sc;
    }
    __syncthreads();
    int r0 = blockIdx.x * 64;
    int r1 = min(r0 + 64, N_NODES);
    float sc = sscale[tid];
    float sh = sshift[tid];
    for (int r = r0; r < r1; r++) {
        size_t idx = (size_t)r * HID + tid;
        float v = h[idx] * sc + sh;
        float o = (v > 0.0f) ? v : expm1f(v);
        if (write_mode == 1) {
            out[idx] = o;
        } else {
            g_A[(size_t)r * 512 + 256 + tid] = __float2half_rn(o);
        }
    }
}

// ---------------- launch ----------------
extern "C" void kernel_launch(void* const* d_in, const int* in_sizes, int n_in,
                              void* d_out, int out_size) {
    (void)in_sizes; (void)n_in; (void)out_size;
    const float* x  = (const float*)d_in[0];
    const int*   ei = (const int*)d_in[1];
    const float* Wn[3] = {(const float*)d_in[2], (const float*)d_in[7],  (const float*)d_in[12]};
    const float* bn[3] = {(const float*)d_in[3], (const float*)d_in[8],  (const float*)d_in[13]};
    const float* Wr[3] = {(const float*)d_in[4], (const float*)d_in[9],  (const float*)d_in[14]};
    const float* gg[3] = {(const float*)d_in[5], (const float*)d_in[10], (const float*)d_in[15]};
    const float* bb[3] = {(const float*)d_in[6], (const float*)d_in[11], (const float*)d_in[16]};
    float* out = (float*)d_out;

    float *h_p, *stats_p;
    __half *A_p, *B_p;
    cudaGetSymbolAddress((void**)&h_p,     g_h);
    cudaGetSymbolAddress((void**)&stats_p, g_stats);
    cudaGetSymbolAddress((void**)&A_p,     g_A);
    cudaGetSymbolAddress((void**)&B_p,     g_B);

    cudaFuncSetAttribute(hmma_gemm_kernel<256>, cudaFuncAttributeMaxDynamicSharedMemorySize, SM_GEMM);
    cudaFuncSetAttribute(hmma_gemm_kernel<512>, cudaFuncAttributeMaxDynamicSharedMemorySize, SM_GEMM);

    const int TB = 256;
    const int nb_edges = (N_EDGES + TB - 1) / TB;
    const int agg_blocks = (N_NODES * 32 + TB - 1) / TB;
    dim3 gemm_grid((N_NODES + 127) / 128, 2);
    const int setup_blocks = 3125 + 6250 + 1536 + 6;   // count | convert_x | convert_w | stats

    // ---- fused setup (count + converts + stats-zero; cursor pre-zeroed by prior call) ----
    setup_kernel<<<setup_blocks, TB>>>(ei, x, Wn[0], Wr[0], Wn[1], Wr[1], Wn[2], Wr[2]);
    scan1_kernel<<<SCAN_NB, 1024>>>();
    scan23_kernel<<<SCAN_NB, 1024>>>();
    scatter_kernel<<<nb_edges, TB>>>(ei);

    // ---- layer 0 (KEXT=256) ----
    agg0_kernel<<<agg_blocks, TB>>>();
    hmma_gemm_kernel<256><<<gemm_grid, 256, SM_GEMM>>>(A_p, B_p, bn[0], h_p, stats_p);
    norm_elu_kernel<<<NORM_BLOCKS, HID>>>(h_p, gg[0], bb[0], stats_p, nullptr, 0);

    // ---- layer 1 (KEXT=512) ----
    agg_bf_kernel<<<agg_blocks, TB>>>();
    hmma_gemm_kernel<512><<<gemm_grid, 256, SM_GEMM>>>(A_p, B_p + 131072, bn[1], h_p, stats_p + 512);
    norm_elu_kernel<<<NORM_BLOCKS, HID>>>(h_p, gg[1], bb[1], stats_p + 512, nullptr, 0);

    // ---- layer 2 (KEXT=512) + tail blocks re-zero g_cursor for next call ----
    agg_bf_kernel<<<agg_blocks, TB>>>();
    hmma_gemm_kernel<512><<<gemm_grid, 256, SM_GEMM>>>(A_p, B_p + 2 * 131072, bn[2], out, stats_p + 1024);
    norm_elu_kernel<<<NORM_BLOCKS + CURSOR_BLOCKS, HID>>>(out, gg[2], bb[2], stats_p + 1024, out, 1);
}